// round 3
// baseline (speedup 1.0000x reference)
#include <cuda_runtime.h>

#define LN_EPS 1e-5f
#define ROWS_PER_BLOCK 8   // 8 warps/block, 256 threads

// One warp per row. D = 128 floats = 32 lanes x float4.
__global__ void __launch_bounds__(256) typenorm_kernel(
    const int*    __restrict__ types,   // type_list (read as int32; safe either dtype)
    const float4* __restrict__ x,       // [N, 32] float4 view of [N,128] f32
    const float4* __restrict__ gamma,   // [T, 32]
    const float4* __restrict__ beta,    // [T, 32]
    float4*       __restrict__ out,     // [N, 32]
    int n_rows)
{
    const int warp_in_block = threadIdx.x >> 5;
    const int lane          = threadIdx.x & 31;
    const int row           = blockIdx.x * ROWS_PER_BLOCK + warp_in_block;
    if (row >= n_rows) return;

    // Coalesced 16B load: lane l gets elements [4l, 4l+4) of the row.
    const float4 v = x[row * 32 + lane];

    float s  = v.x + v.y + v.z + v.w;
    float ss = v.x * v.x + v.y * v.y + v.z * v.z + v.w * v.w;

    // Warp tree reduction over 32 lanes.
    #pragma unroll
    for (int off = 16; off > 0; off >>= 1) {
        s  += __shfl_xor_sync(0xFFFFFFFFu, s,  off);
        ss += __shfl_xor_sync(0xFFFFFFFFu, ss, off);
    }

    const float inv_d = 1.0f / 128.0f;
    const float mean  = s * inv_d;
    const float var   = fmaf(ss, inv_d, -mean * mean);  // E[x^2] - mean^2 (biased)
    const float rstd  = rsqrtf(var + LN_EPS);

    // Type-indexed affine params (4 KB tables -> L1/L2 resident).
    const int t = __ldg(&types[row]);
    const float4 g = __ldg(&gamma[t * 32 + lane]);
    const float4 b = __ldg(&beta [t * 32 + lane]);

    float4 o;
    o.x = fmaf((v.x - mean) * rstd, g.x, b.x);
    o.y = fmaf((v.y - mean) * rstd, g.y, b.y);
    o.z = fmaf((v.z - mean) * rstd, g.z, b.z);
    o.w = fmaf((v.w - mean) * rstd, g.w, b.w);

    out[row * 32 + lane] = o;
}

extern "C" void kernel_launch(void* const* d_in, const int* in_sizes, int n_in,
                              void* d_out, int out_size)
{
    // Inputs in reference order: type_list, abstract_features, gamma, beta
    const int*    types = (const int*)   d_in[0];
    const float4* x     = (const float4*)d_in[1];
    const float4* gamma = (const float4*)d_in[2];
    const float4* beta  = (const float4*)d_in[3];
    float4*       out   = (float4*)      d_out;

    const int n_rows = in_sizes[1] / 128;   // abstract_features elements / D

    const int blocks = (n_rows + ROWS_PER_BLOCK - 1) / ROWS_PER_BLOCK;
    typenorm_kernel<<<blocks, 256>>>(types, x, gamma, beta, out, n_rows);
}

// round 4
// speedup vs baseline: 1.1152x; 1.1152x over previous
#include <cuda_runtime.h>

#define LN_EPS 1e-5f

// 8 lanes per row, 4 rows per warp, 8 warps per block => 32 rows/block.
// Each thread loads 4x float4 (16 floats) from its row: high MLP, exact
// cache-line coalescing (each LDG.128 instruction = 4 rows x 128B lines).
__global__ void __launch_bounds__(256) typenorm_kernel(
    const int*    __restrict__ types,   // type_list (int32 view)
    const float4* __restrict__ x,       // [N, 32] float4 view of [N,128] f32
    const float4* __restrict__ gamma,   // [T, 32]
    const float4* __restrict__ beta,    // [T, 32]
    float4*       __restrict__ out,     // [N, 32]
    int n_rows)
{
    const int warp = threadIdx.x >> 5;
    const int lane = threadIdx.x & 31;
    const int sub  = lane & 7;          // position within row (8 lanes/row)
    const int r    = lane >> 3;         // which of the warp's 4 rows

    const int row = (blockIdx.x << 5) + (warp << 2) + r;
    if (row >= n_rows) return;

    const float4* xr = x + row * 32;

    // Front-batched independent loads: MLP=4 per thread.
    float4 v0 = xr[sub +  0];
    float4 v1 = xr[sub +  8];
    float4 v2 = xr[sub + 16];
    float4 v3 = xr[sub + 24];

    // Local accumulation over 16 elements (replaces 2 shuffle levels).
    float s  = ((v0.x + v0.y) + (v0.z + v0.w)) + ((v1.x + v1.y) + (v1.z + v1.w))
             + ((v2.x + v2.y) + (v2.z + v2.w)) + ((v3.x + v3.y) + (v3.z + v3.w));
    float ss = v0.x*v0.x + v0.y*v0.y + v0.z*v0.z + v0.w*v0.w
             + v1.x*v1.x + v1.y*v1.y + v1.z*v1.z + v1.w*v1.w
             + v2.x*v2.x + v2.y*v2.y + v2.z*v2.z + v2.w*v2.w
             + v3.x*v3.x + v3.y*v3.y + v3.z*v3.z + v3.w*v3.w;

    // Cross-lane reduction within aligned 8-lane group: 3 steps only.
    #pragma unroll
    for (int off = 4; off > 0; off >>= 1) {
        s  += __shfl_xor_sync(0xFFFFFFFFu, s,  off);
        ss += __shfl_xor_sync(0xFFFFFFFFu, ss, off);
    }

    const float inv_d = 1.0f / 128.0f;
    const float mean  = s * inv_d;
    const float var   = fmaf(ss, inv_d, -mean * mean);  // biased variance
    const float rstd  = rsqrtf(var + LN_EPS);

    // Type-indexed affine params: 4 KB tables, L1/L2 resident.
    const int t = __ldg(&types[row]);
    const float4* gr = gamma + t * 32;
    const float4* br = beta  + t * 32;

    float4 g0 = __ldg(&gr[sub +  0]);
    float4 g1 = __ldg(&gr[sub +  8]);
    float4 g2 = __ldg(&gr[sub + 16]);
    float4 g3 = __ldg(&gr[sub + 24]);
    float4 b0 = __ldg(&br[sub +  0]);
    float4 b1 = __ldg(&br[sub +  8]);
    float4 b2 = __ldg(&br[sub + 16]);
    float4 b3 = __ldg(&br[sub + 24]);

    float4* outr = out + row * 32;
    float4 o;

    o.x = fmaf((v0.x - mean) * rstd, g0.x, b0.x);
    o.y = fmaf((v0.y - mean) * rstd, g0.y, b0.y);
    o.z = fmaf((v0.z - mean) * rstd, g0.z, b0.z);
    o.w = fmaf((v0.w - mean) * rstd, g0.w, b0.w);
    outr[sub + 0] = o;

    o.x = fmaf((v1.x - mean) * rstd, g1.x, b1.x);
    o.y = fmaf((v1.y - mean) * rstd, g1.y, b1.y);
    o.z = fmaf((v1.z - mean) * rstd, g1.z, b1.z);
    o.w = fmaf((v1.w - mean) * rstd, g1.w, b1.w);
    outr[sub + 8] = o;

    o.x = fmaf((v2.x - mean) * rstd, g2.x, b2.x);
    o.y = fmaf((v2.y - mean) * rstd, g2.y, b2.y);
    o.z = fmaf((v2.z - mean) * rstd, g2.z, b2.z);
    o.w = fmaf((v2.w - mean) * rstd, g2.w, b2.w);
    outr[sub + 16] = o;

    o.x = fmaf((v3.x - mean) * rstd, g3.x, b3.x);
    o.y = fmaf((v3.y - mean) * rstd, g3.y, b3.y);
    o.z = fmaf((v3.z - mean) * rstd, g3.z, b3.z);
    o.w = fmaf((v3.w - mean) * rstd, g3.w, b3.w);
    outr[sub + 24] = o;
}

extern "C" void kernel_launch(void* const* d_in, const int* in_sizes, int n_in,
                              void* d_out, int out_size)
{
    const int*    types = (const int*)   d_in[0];
    const float4* x     = (const float4*)d_in[1];
    const float4* gamma = (const float4*)d_in[2];
    const float4* beta  = (const float4*)d_in[3];
    float4*       out   = (float4*)      d_out;

    const int n_rows = in_sizes[1] / 128;

    const int rows_per_block = 32;
    const int blocks = (n_rows + rows_per_block - 1) / rows_per_block;
    typenorm_kernel<<<blocks, 256>>>(types, x, gamma, beta, out, n_rows);
}

// round 5
// speedup vs baseline: 1.1194x; 1.0037x over previous
#include <cuda_runtime.h>

#define LN_EPS 1e-5f

// 8 lanes per row, 4 rows per warp, 8 warps per block => 32 rows/block.
// Each thread loads 4x float4 (16 floats) from its row: MLP=4, exact
// cache-line coalescing. Streaming cache hints (__ldcs/__stcs) mark the
// 2 GB single-touch x/out traffic evict-first in L2.
__global__ void __launch_bounds__(256) typenorm_kernel(
    const int*    __restrict__ types,   // type_list (int32 view)
    const float4* __restrict__ x,       // [N, 32] float4 view of [N,128] f32
    const float4* __restrict__ gamma,   // [T, 32]
    const float4* __restrict__ beta,    // [T, 32]
    float4*       __restrict__ out,     // [N, 32]
    int n_rows)
{
    const int warp = threadIdx.x >> 5;
    const int lane = threadIdx.x & 31;
    const int sub  = lane & 7;          // position within row (8 lanes/row)
    const int r    = lane >> 3;         // which of the warp's 4 rows

    const int row = (blockIdx.x << 5) + (warp << 2) + r;
    if (row >= n_rows) return;

    const float4* xr = x + row * 32;

    // Front-batched independent streaming loads: MLP=4 per thread.
    float4 v0 = __ldcs(&xr[sub +  0]);
    float4 v1 = __ldcs(&xr[sub +  8]);
    float4 v2 = __ldcs(&xr[sub + 16]);
    float4 v3 = __ldcs(&xr[sub + 24]);

    // Local accumulation over 16 elements.
    float s  = ((v0.x + v0.y) + (v0.z + v0.w)) + ((v1.x + v1.y) + (v1.z + v1.w))
             + ((v2.x + v2.y) + (v2.z + v2.w)) + ((v3.x + v3.y) + (v3.z + v3.w));
    float ss = v0.x*v0.x + v0.y*v0.y + v0.z*v0.z + v0.w*v0.w
             + v1.x*v1.x + v1.y*v1.y + v1.z*v1.z + v1.w*v1.w
             + v2.x*v2.x + v2.y*v2.y + v2.z*v2.z + v2.w*v2.w
             + v3.x*v3.x + v3.y*v3.y + v3.z*v3.z + v3.w*v3.w;

    // Cross-lane reduction within aligned 8-lane group: 3 steps.
    #pragma unroll
    for (int off = 4; off > 0; off >>= 1) {
        s  += __shfl_xor_sync(0xFFFFFFFFu, s,  off);
        ss += __shfl_xor_sync(0xFFFFFFFFu, ss, off);
    }

    const float inv_d = 1.0f / 128.0f;
    const float mean  = s * inv_d;
    const float var   = fmaf(ss, inv_d, -mean * mean);  // biased variance
    const float rstd  = rsqrtf(var + LN_EPS);

    // Type-indexed affine params: 4 KB tables, default caching (L1/L2 resident).
    const int t = __ldg(&types[row]);
    const float4* gr = gamma + t * 32;
    const float4* br = beta  + t * 32;

    float4 g0 = __ldg(&gr[sub +  0]);
    float4 g1 = __ldg(&gr[sub +  8]);
    float4 g2 = __ldg(&gr[sub + 16]);
    float4 g3 = __ldg(&gr[sub + 24]);
    float4 b0 = __ldg(&br[sub +  0]);
    float4 b1 = __ldg(&br[sub +  8]);
    float4 b2 = __ldg(&br[sub + 16]);
    float4 b3 = __ldg(&br[sub + 24]);

    float4* outr = out + row * 32;
    float4 o;

    o.x = fmaf((v0.x - mean) * rstd, g0.x, b0.x);
    o.y = fmaf((v0.y - mean) * rstd, g0.y, b0.y);
    o.z = fmaf((v0.z - mean) * rstd, g0.z, b0.z);
    o.w = fmaf((v0.w - mean) * rstd, g0.w, b0.w);
    __stcs(&outr[sub + 0], o);

    o.x = fmaf((v1.x - mean) * rstd, g1.x, b1.x);
    o.y = fmaf((v1.y - mean) * rstd, g1.y, b1.y);
    o.z = fmaf((v1.z - mean) * rstd, g1.z, b1.z);
    o.w = fmaf((v1.w - mean) * rstd, g1.w, b1.w);
    __stcs(&outr[sub + 8], o);

    o.x = fmaf((v2.x - mean) * rstd, g2.x, b2.x);
    o.y = fmaf((v2.y - mean) * rstd, g2.y, b2.y);
    o.z = fmaf((v2.z - mean) * rstd, g2.z, b2.z);
    o.w = fmaf((v2.w - mean) * rstd, g2.w, b2.w);
    __stcs(&outr[sub + 16], o);

    o.x = fmaf((v3.x - mean) * rstd, g3.x, b3.x);
    o.y = fmaf((v3.y - mean) * rstd, g3.y, b3.y);
    o.z = fmaf((v3.z - mean) * rstd, g3.z, b3.z);
    o.w = fmaf((v3.w - mean) * rstd, g3.w, b3.w);
    __stcs(&outr[sub + 24], o);
}

extern "C" void kernel_launch(void* const* d_in, const int* in_sizes, int n_in,
                              void* d_out, int out_size)
{
    const int*    types = (const int*)   d_in[0];
    const float4* x     = (const float4*)d_in[1];
    const float4* gamma = (const float4*)d_in[2];
    const float4* beta  = (const float4*)d_in[3];
    float4*       out   = (float4*)      d_out;

    const int n_rows = in_sizes[1] / 128;

    const int rows_per_block = 32;
    const int blocks = (n_rows + rows_per_block - 1) / rows_per_block;
    typenorm_kernel<<<blocks, 256>>>(types, x, gamma, beta, out, n_rows);
}